// round 11
// baseline (speedup 1.0000x reference)
#include <cuda_runtime.h>
#include <cuda_fp16.h>
#include <cstdint>

#define NN 20000
#define NE 320000
#define NB 32
#define HDIM 64
#define HC 256   // H*C
#define NH 4
#define NL 3

// ---------------- scratch (device globals; no allocation allowed) ----------
__device__ int    g_deg[NN];
__device__ int    g_rowptr[NN + 1];
__device__ int    g_fill[NN];
__device__ int    g_csrc[NE];
__device__ __half g_hh[NN * HDIM];         // fp16 node features (layer input)
__device__ __half g_Wh[NL * HDIM * HC];    // fp16 conv weights
__device__ __half g_xph[NN * HC];          // fp16 projected features
__device__ float  g_as[NN * NH];
__device__ float  g_ad[NN * NH];
__device__ float  g_aedeP[NL * NE * 4];    // per-layer planes of edge logits, CSR order
__device__ float  g_aeds[NN * 12];         // self-loop logit sums (divided by deg at read)
__device__ float  g_weatt[HDIM * 12];
__device__ float  g_pool[NB * HDIM];
__device__ int    g_cnt[NB];

__device__ __forceinline__ float lrelu(float x) { return x > 0.f ? x : 0.2f * x; }

// ---------------- combined pre-kernel ---------------------------------------
#define PRE_WEATT_BLOCKS 96
__global__ __launch_bounds__(256) void pre_kernel(const int* __restrict__ dst,
                                                  const float* __restrict__ x,
                                                  const float* __restrict__ node_W,
                                                  const float* __restrict__ node_b,
                                                  const float* __restrict__ lin_eW,
                                                  const float* __restrict__ att_e,
                                                  const float* __restrict__ lin_W) {
    if (blockIdx.x < PRE_WEATT_BLOCKS) {
        int wid = (blockIdx.x * 256 + threadIdx.x) >> 5;
        int lane = threadIdx.x & 31;
        if (wid >= NL * HDIM * NH) return;
        int l = wid >> 8;
        int rem = wid & 255;
        int d = rem >> 2;
        int h = rem & 3;
        const float* w = lin_eW + l * HDIM * HC + d * HC + h * 64;
        const float* a = att_e + l * NH * 64 + h * 64;
        float s = w[lane] * a[lane] + w[32 + lane] * a[32 + lane];
        #pragma unroll
        for (int off = 16; off >= 1; off >>= 1) s += __shfl_xor_sync(0xffffffffu, s, off);
        if (lane == 0) g_weatt[d * 12 + l * 4 + h] = s;
        return;
    }
    int idx = (blockIdx.x - PRE_WEATT_BLOCKS) * 256 + threadIdx.x;
    if (idx < NE) atomicAdd(&g_deg[dst[idx]], 1);
    if (idx < NN * 12) g_aeds[idx] = 0.f;
    if (idx < NB * HDIM) g_pool[idx] = 0.f;
    if (idx < NB) g_cnt[idx] = 0;
    if (idx < NL * HDIM * HC / 2) {
        float2 wv = *(const float2*)&lin_W[idx * 2];
        *(__half2*)&g_Wh[idx * 2] = __floats2half2_rn(wv.x, wv.y);
    }
    if (idx < NN * HDIM) {
        int n = idx >> 6, c = idx & 63;
        float v = x[n * 3 + 0] * node_W[c] + x[n * 3 + 1] * node_W[64 + c]
                + x[n * 3 + 2] * node_W[128 + c] + node_b[c];
        g_hh[idx] = __float2half(fmaxf(v, 0.f));
    }
}

// ---------------- scan: single block, 20 elements per thread ---------------
__global__ __launch_bounds__(1024) void scan_kernel() {
    __shared__ int wsum[32];
    const int PER = 20;
    int t = threadIdx.x;
    int lane = t & 31, w = t >> 5;
    int v[PER];
    int sum = 0;
    int base = t * PER;
    if (t < 1000) {
        #pragma unroll
        for (int i = 0; i < PER; i++) {
            sum += g_deg[base + i];
            v[i] = sum;
        }
    }
    int x = sum;
    #pragma unroll
    for (int off = 1; off < 32; off <<= 1) {
        int y = __shfl_up_sync(0xffffffffu, x, off);
        if (lane >= off) x += y;
    }
    if (lane == 31) wsum[w] = x;
    __syncthreads();
    if (w == 0) {
        int y = wsum[lane];
        #pragma unroll
        for (int off = 1; off < 32; off <<= 1) {
            int z = __shfl_up_sync(0xffffffffu, y, off);
            if (lane >= off) y += z;
        }
        wsum[lane] = y;
    }
    __syncthreads();
    int prefix = x - sum + (w > 0 ? wsum[w - 1] : 0);
    if (t < 1000) {
        if (t == 0) g_rowptr[0] = 0;
        #pragma unroll
        for (int i = 0; i < PER; i++) g_rowptr[base + i + 1] = prefix + v[i];
    }
}

// ---- edge embedding -> 12 logits, fused CSR scatter; 2 edges per thread ----
__global__ __launch_bounds__(256) void edge_emb_kernel(const float* __restrict__ eattr,
                                                       const int* __restrict__ src,
                                                       const int* __restrict__ dst,
                                                       const float* __restrict__ eemb_W,
                                                       const float* __restrict__ eemb_b) {
    __shared__ float4 sW4[64];
    __shared__ float  sb64[64];
    __shared__ float4 sA4[64 * 3];
    int t = threadIdx.x;
    if (t < 64) {
        sW4[t] = make_float4(eemb_W[t], eemb_W[64 + t], eemb_W[128 + t], eemb_W[192 + t]);
        sb64[t] = eemb_b[t];
    }
    for (int i = t; i < 64 * 3; i += 256) sA4[i] = ((const float4*)g_weatt)[i];
    __syncthreads();

    int e0 = blockIdx.x * blockDim.x + t;
    if (e0 >= NE / 2) return;
    int e1 = e0 + NE / 2;
    float4 a0 = *(const float4*)&eattr[e0 * 4];
    float4 a1 = *(const float4*)&eattr[e1 * 4];
    float d0a[12], d1a[12];
    #pragma unroll
    for (int o = 0; o < 12; o++) { d0a[o] = 0.f; d1a[o] = 0.f; }
    #pragma unroll 4
    for (int d = 0; d < 64; d++) {
        float4 w = sW4[d];
        float bb = sb64[d];
        float ea0 = fmaxf(a0.x * w.x + a0.y * w.y + a0.z * w.z + a0.w * w.w + bb, 0.f);
        float ea1 = fmaxf(a1.x * w.x + a1.y * w.y + a1.z * w.z + a1.w * w.w + bb, 0.f);
        float4 A0 = sA4[d * 3 + 0], A1 = sA4[d * 3 + 1], A2 = sA4[d * 3 + 2];
        d0a[0] += ea0 * A0.x; d0a[1] += ea0 * A0.y; d0a[2]  += ea0 * A0.z; d0a[3]  += ea0 * A0.w;
        d0a[4] += ea0 * A1.x; d0a[5] += ea0 * A1.y; d0a[6]  += ea0 * A1.z; d0a[7]  += ea0 * A1.w;
        d0a[8] += ea0 * A2.x; d0a[9] += ea0 * A2.y; d0a[10] += ea0 * A2.z; d0a[11] += ea0 * A2.w;
        d1a[0] += ea1 * A0.x; d1a[1] += ea1 * A0.y; d1a[2]  += ea1 * A0.z; d1a[3]  += ea1 * A0.w;
        d1a[4] += ea1 * A1.x; d1a[5] += ea1 * A1.y; d1a[6]  += ea1 * A1.z; d1a[7]  += ea1 * A1.w;
        d1a[8] += ea1 * A2.x; d1a[9] += ea1 * A2.y; d1a[10] += ea1 * A2.z; d1a[11] += ea1 * A2.w;
    }
    float4* P = (float4*)g_aedeP;
    {
        int dn = dst[e0], sn = src[e0];
        int slot = g_rowptr[dn] + atomicAdd(&g_fill[dn], 1);
        g_csrc[slot] = sn;
        P[0 * NE + slot] = make_float4(d0a[0], d0a[1], d0a[2],  d0a[3]);
        P[1 * NE + slot] = make_float4(d0a[4], d0a[5], d0a[6],  d0a[7]);
        P[2 * NE + slot] = make_float4(d0a[8], d0a[9], d0a[10], d0a[11]);
        #pragma unroll
        for (int o = 0; o < 12; o++) atomicAdd(&g_aeds[dn * 12 + o], d0a[o]);
    }
    {
        int dn = dst[e1], sn = src[e1];
        int slot = g_rowptr[dn] + atomicAdd(&g_fill[dn], 1);
        g_csrc[slot] = sn;
        P[0 * NE + slot] = make_float4(d1a[0], d1a[1], d1a[2],  d1a[3]);
        P[1 * NE + slot] = make_float4(d1a[4], d1a[5], d1a[6],  d1a[7]);
        P[2 * NE + slot] = make_float4(d1a[8], d1a[9], d1a[10], d1a[11]);
        #pragma unroll
        for (int o = 0; o < 12; o++) atomicAdd(&g_aeds[dn * 12 + o], d1a[o]);
    }
}

// ---------------- tensor-core GEMM + fused a_s/a_d --------------------------
__device__ __forceinline__ void mma16816(float& c0, float& c1, float& c2, float& c3,
                                         uint32_t a0, uint32_t a1, uint32_t a2, uint32_t a3,
                                         uint32_t b0, uint32_t b1) {
    asm volatile(
        "mma.sync.aligned.m16n8k16.row.col.f32.f16.f16.f32 "
        "{%0,%1,%2,%3},{%4,%5,%6,%7},{%8,%9},{%0,%1,%2,%3};"
        : "+f"(c0), "+f"(c1), "+f"(c2), "+f"(c3)
        : "r"(a0), "r"(a1), "r"(a2), "r"(a3), "r"(b0), "r"(b1));
}

#define BPAD 264   // 256 + 8 halves

__global__ __launch_bounds__(512) void gemm_attn_kernel(int layer,
                                                        const float* __restrict__ att_src,
                                                        const float* __restrict__ att_dst) {
    __shared__ __half Ah[64][72];
    __shared__ __half Bh[64][BPAD];
    __shared__ float  sAs[256], sAd[256];

    int tid = threadIdx.x;
    int warp = tid >> 5, lane = tid & 31;
    int n0 = blockIdx.x * 64;

    if (tid < 256) { sAs[tid] = att_src[tid]; sAd[tid] = att_dst[tid]; }

    {
        int row = tid >> 3, cb = (tid & 7) * 8;
        uint4 v = make_uint4(0u, 0u, 0u, 0u);
        if (n0 + row < NN) v = *(const uint4*)&g_hh[(size_t)(n0 + row) * HDIM + cb];
        *(uint4*)&Ah[row][cb] = v;
    }
    {
        int kr = tid >> 3, cb = (tid & 7) * 32;
        const uint4* srcp = (const uint4*)&g_Wh[(size_t)layer * HDIM * HC + (size_t)kr * HC + cb];
        uint4* dstp = (uint4*)&Bh[kr][cb];
        dstp[0] = srcp[0];
        dstp[1] = srcp[1];
        dstp[2] = srcp[2];
        dstp[3] = srcp[3];
    }
    __syncthreads();

    int wm = warp & 3, wn = warp >> 2;        // wn = head
    int mrow = wm * 16;
    int ncol0 = wn * 64;

    uint32_t afr[4][4];
    {
        int r = mrow + (lane & 7) + ((lane >> 3) & 1) * 8;
        int kc = ((lane >> 4) & 1) * 8;
        #pragma unroll
        for (int ks = 0; ks < 4; ks++) {
            unsigned addr = (unsigned)__cvta_generic_to_shared(&Ah[r][ks * 16 + kc]);
            asm volatile("ldmatrix.sync.aligned.m8n8.x4.shared.b16 {%0,%1,%2,%3}, [%4];"
                         : "=r"(afr[ks][0]), "=r"(afr[ks][1]), "=r"(afr[ks][2]), "=r"(afr[ks][3])
                         : "r"(addr));
        }
    }

    float acc[8][4];
    #pragma unroll
    for (int nt = 0; nt < 8; nt++)
        #pragma unroll
        for (int j = 0; j < 4; j++) acc[nt][j] = 0.f;

    int bl8 = lane & 7, bm2 = (lane >> 3) & 1;
    #pragma unroll
    for (int nt = 0; nt < 8; nt++) {
        int ncol = ncol0 + nt * 8;
        #pragma unroll
        for (int ks = 0; ks < 4; ks++) {
            unsigned addr = (unsigned)__cvta_generic_to_shared(&Bh[ks * 16 + bl8 + bm2 * 8][ncol]);
            uint32_t b0, b1;
            asm volatile("ldmatrix.sync.aligned.m8n8.x2.trans.shared.b16 {%0,%1}, [%2];"
                         : "=r"(b0), "=r"(b1) : "r"(addr));
            mma16816(acc[nt][0], acc[nt][1], acc[nt][2], acc[nt][3],
                     afr[ks][0], afr[ks][1], afr[ks][2], afr[ks][3], b0, b1);
        }
    }

    // a_s/a_d from fragments (warp cols == head wn)
    {
        int c0 = ncol0 + (lane & 3) * 2;
        int row0 = mrow + (lane >> 2);
        float sp0 = 0.f, sp1 = 0.f, dp0 = 0.f, dp1 = 0.f;
        #pragma unroll
        for (int nt = 0; nt < 8; nt++) {
            float a0 = sAs[c0 + nt * 8], a1 = sAs[c0 + nt * 8 + 1];
            float d0 = sAd[c0 + nt * 8], d1 = sAd[c0 + nt * 8 + 1];
            sp0 += acc[nt][0] * a0 + acc[nt][1] * a1;
            sp1 += acc[nt][2] * a0 + acc[nt][3] * a1;
            dp0 += acc[nt][0] * d0 + acc[nt][1] * d1;
            dp1 += acc[nt][2] * d0 + acc[nt][3] * d1;
        }
        #pragma unroll
        for (int off = 1; off <= 2; off <<= 1) {
            sp0 += __shfl_xor_sync(0xffffffffu, sp0, off);
            sp1 += __shfl_xor_sync(0xffffffffu, sp1, off);
            dp0 += __shfl_xor_sync(0xffffffffu, dp0, off);
            dp1 += __shfl_xor_sync(0xffffffffu, dp1, off);
        }
        if ((lane & 3) == 0) {
            if (n0 + row0 < NN) {
                g_as[(n0 + row0) * 4 + wn] = sp0;
                g_ad[(n0 + row0) * 4 + wn] = dp0;
            }
            if (n0 + row0 + 8 < NN) {
                g_as[(n0 + row0 + 8) * 4 + wn] = sp1;
                g_ad[(n0 + row0 + 8) * 4 + wn] = dp1;
            }
        }
    }

    // direct xp stores from fragments
    {
        int r0g = n0 + mrow + (lane >> 2);
        int c0 = ncol0 + (lane & 3) * 2;
        #pragma unroll
        for (int nt = 0; nt < 8; nt++) {
            if (r0g < NN)
                *(__half2*)&g_xph[(size_t)r0g * HC + c0 + nt * 8] =
                    __floats2half2_rn(acc[nt][0], acc[nt][1]);
            if (r0g + 8 < NN)
                *(__half2*)&g_xph[(size_t)(r0g + 8) * HC + c0 + nt * 8] =
                    __floats2half2_rn(acc[nt][2], acc[nt][3]);
        }
    }
}

// ---- softmax + aggregation, TWO nodes per warp (interleaved, MLP x2) -------
__global__ __launch_bounds__(256) void aggr_kernel(const float* __restrict__ conv_b, int layer,
                                                   const int* __restrict__ batch) {
    int wg = (blockIdx.x * blockDim.x + threadIdx.x) >> 5;
    if (wg >= NN / 2) return;
    int lane = threadIdx.x & 31;
    int nA = wg * 2, nB = nA + 1;

    int begA = g_rowptr[nA], endA = g_rowptr[nA + 1];
    int begB = g_rowptr[nB], endB = g_rowptr[nB + 1];

    float4 advA = *(const float4*)&g_ad[nA * 4];
    float4 aslA = *(const float4*)&g_as[nA * 4];
    float4 aesA = *(const float4*)&g_aeds[nA * 12 + layer * 4];
    float4 advB = *(const float4*)&g_ad[nB * 4];
    float4 aslB = *(const float4*)&g_as[nB * 4];
    float4 aesB = *(const float4*)&g_aeds[nB * 12 + layer * 4];
    float ivA = 1.f / fmaxf((float)(endA - begA), 1.f);
    float ivB = 1.f / fmaxf((float)(endB - begB), 1.f);

    float exA0 = __expf(lrelu(aslA.x + advA.x + aesA.x * ivA));
    float exA1 = __expf(lrelu(aslA.y + advA.y + aesA.y * ivA));
    float exA2 = __expf(lrelu(aslA.z + advA.z + aesA.z * ivA));
    float exA3 = __expf(lrelu(aslA.w + advA.w + aesA.w * ivA));
    float exB0 = __expf(lrelu(aslB.x + advB.x + aesB.x * ivB));
    float exB1 = __expf(lrelu(aslB.y + advB.y + aesB.y * ivB));
    float exB2 = __expf(lrelu(aslB.z + advB.z + aesB.z * ivB));
    float exB3 = __expf(lrelu(aslB.w + advB.w + aesB.w * ivB));

    float dA0 = 0.f, dA1 = 0.f, dA2 = 0.f, dA3 = 0.f;
    float dB0 = 0.f, dB1 = 0.f, dB2 = 0.f, dB3 = 0.f;
    float accA[8], accB[8];
    {
        const __half2* xr = (const __half2*)(g_xph + (size_t)nA * HC) + lane;
        float2 p0 = __half22float2(xr[0]);
        float2 p1 = __half22float2(xr[32]);
        float2 p2 = __half22float2(xr[64]);
        float2 p3 = __half22float2(xr[96]);
        accA[0] = exA0 * p0.x; accA[1] = exA0 * p0.y;
        accA[2] = exA1 * p1.x; accA[3] = exA1 * p1.y;
        accA[4] = exA2 * p2.x; accA[5] = exA2 * p2.y;
        accA[6] = exA3 * p3.x; accA[7] = exA3 * p3.y;
    }
    {
        const __half2* xr = (const __half2*)(g_xph + (size_t)nB * HC) + lane;
        float2 p0 = __half22float2(xr[0]);
        float2 p1 = __half22float2(xr[32]);
        float2 p2 = __half22float2(xr[64]);
        float2 p3 = __half22float2(xr[96]);
        accB[0] = exB0 * p0.x; accB[1] = exB0 * p0.y;
        accB[2] = exB1 * p1.x; accB[3] = exB1 * p1.y;
        accB[4] = exB2 * p2.x; accB[5] = exB2 * p2.y;
        accB[6] = exB3 * p3.x; accB[7] = exB3 * p3.y;
    }

    const float4* plane = (const float4*)g_aedeP + (size_t)layer * NE;
    int baseA = begA, baseB = begB;
    while (baseA < endA || baseB < endB) {
        int cntA = max(0, min(32, endA - baseA));
        int cntB = max(0, min(32, endB - baseB));
        float fA0 = 0.f, fA1 = 0.f, fA2 = 0.f, fA3 = 0.f;
        float fB0 = 0.f, fB1 = 0.f, fB2 = 0.f, fB3 = 0.f;
        int ssA = 0, ssB = 0;
        if (lane < cntA) {
            int e = baseA + lane;
            ssA = g_csrc[e];
            float4 av = *(const float4*)&g_as[ssA * 4];
            float4 ae = plane[e];
            fA0 = __expf(lrelu(av.x + advA.x + ae.x));
            fA1 = __expf(lrelu(av.y + advA.y + ae.y));
            fA2 = __expf(lrelu(av.z + advA.z + ae.z));
            fA3 = __expf(lrelu(av.w + advA.w + ae.w));
        }
        if (lane < cntB) {
            int e = baseB + lane;
            ssB = g_csrc[e];
            float4 av = *(const float4*)&g_as[ssB * 4];
            float4 ae = plane[e];
            fB0 = __expf(lrelu(av.x + advB.x + ae.x));
            fB1 = __expf(lrelu(av.y + advB.y + ae.y));
            fB2 = __expf(lrelu(av.z + advB.z + ae.z));
            fB3 = __expf(lrelu(av.w + advB.w + ae.w));
        }
        dA0 += fA0; dA1 += fA1; dA2 += fA2; dA3 += fA3;
        dB0 += fB0; dB1 += fB1; dB2 += fB2; dB3 += fB3;
        int tmax = max(cntA, cntB);
        for (int t = 0; t < tmax; t++) {
            if (t < cntA) {
                float b0 = __shfl_sync(0xffffffffu, fA0, t);
                float b1 = __shfl_sync(0xffffffffu, fA1, t);
                float b2 = __shfl_sync(0xffffffffu, fA2, t);
                float b3 = __shfl_sync(0xffffffffu, fA3, t);
                int sb = __shfl_sync(0xffffffffu, ssA, t);
                const __half2* xr = (const __half2*)(g_xph + (size_t)sb * HC) + lane;
                float2 p0 = __half22float2(xr[0]);
                float2 p1 = __half22float2(xr[32]);
                float2 p2 = __half22float2(xr[64]);
                float2 p3 = __half22float2(xr[96]);
                accA[0] += b0 * p0.x; accA[1] += b0 * p0.y;
                accA[2] += b1 * p1.x; accA[3] += b1 * p1.y;
                accA[4] += b2 * p2.x; accA[5] += b2 * p2.y;
                accA[6] += b3 * p3.x; accA[7] += b3 * p3.y;
            }
            if (t < cntB) {
                float b0 = __shfl_sync(0xffffffffu, fB0, t);
                float b1 = __shfl_sync(0xffffffffu, fB1, t);
                float b2 = __shfl_sync(0xffffffffu, fB2, t);
                float b3 = __shfl_sync(0xffffffffu, fB3, t);
                int sb = __shfl_sync(0xffffffffu, ssB, t);
                const __half2* xr = (const __half2*)(g_xph + (size_t)sb * HC) + lane;
                float2 p0 = __half22float2(xr[0]);
                float2 p1 = __half22float2(xr[32]);
                float2 p2 = __half22float2(xr[64]);
                float2 p3 = __half22float2(xr[96]);
                accB[0] += b0 * p0.x; accB[1] += b0 * p0.y;
                accB[2] += b1 * p1.x; accB[3] += b1 * p1.y;
                accB[4] += b2 * p2.x; accB[5] += b2 * p2.y;
                accB[6] += b3 * p3.x; accB[7] += b3 * p3.y;
            }
        }
        baseA += 32; baseB += 32;
    }
    #pragma unroll
    for (int off = 16; off >= 1; off >>= 1) {
        dA0 += __shfl_xor_sync(0xffffffffu, dA0, off);
        dA1 += __shfl_xor_sync(0xffffffffu, dA1, off);
        dA2 += __shfl_xor_sync(0xffffffffu, dA2, off);
        dA3 += __shfl_xor_sync(0xffffffffu, dA3, off);
        dB0 += __shfl_xor_sync(0xffffffffu, dB0, off);
        dB1 += __shfl_xor_sync(0xffffffffu, dB1, off);
        dB2 += __shfl_xor_sync(0xffffffffu, dB2, off);
        dB3 += __shfl_xor_sync(0xffffffffu, dB3, off);
    }
    dA0 += exA0; dA1 += exA1; dA2 += exA2; dA3 += exA3;
    dB0 += exB0; dB1 += exB1; dB2 += exB2; dB3 += exB3;

    float2 cb = *(const float2*)&conv_b[lane * 2];
    float rA0 = accA[0] / dA0 + accA[2] / dA1 + accA[4] / dA2 + accA[6] / dA3;
    float rA1 = accA[1] / dA0 + accA[3] / dA1 + accA[5] / dA2 + accA[7] / dA3;
    float rB0 = accB[0] / dB0 + accB[2] / dB1 + accB[4] / dB2 + accB[6] / dB3;
    float rB1 = accB[1] / dB0 + accB[3] / dB1 + accB[5] / dB2 + accB[7] / dB3;
    float vA0 = fmaxf(0.25f * rA0 + cb.x, 0.f);
    float vA1 = fmaxf(0.25f * rA1 + cb.y, 0.f);
    float vB0 = fmaxf(0.25f * rB0 + cb.x, 0.f);
    float vB1 = fmaxf(0.25f * rB1 + cb.y, 0.f);
    if (layer < 2) {
        *(__half2*)&g_hh[nA * HDIM + lane * 2] = __floats2half2_rn(vA0, vA1);
        *(__half2*)&g_hh[nB * HDIM + lane * 2] = __floats2half2_rn(vB0, vB1);
    } else {
        int bA = batch[nA];
        int bB = batch[nB];
        atomicAdd(&g_pool[bA * 64 + lane * 2], vA0);
        atomicAdd(&g_pool[bA * 64 + lane * 2 + 1], vA1);
        atomicAdd(&g_pool[bB * 64 + lane * 2], vB0);
        atomicAdd(&g_pool[bB * 64 + lane * 2 + 1], vB1);
        if (lane == 0) { atomicAdd(&g_cnt[bA], 1); atomicAdd(&g_cnt[bB], 1); }
    }
}

// ---------------- head MLP ---------------------------------------------------
__global__ __launch_bounds__(256) void final_kernel(const float* __restrict__ u,
                                                    const float* __restrict__ gW, const float* __restrict__ gb,
                                                    const float* __restrict__ f1W, const float* __restrict__ f1b,
                                                    const float* __restrict__ f2W, const float* __restrict__ f2b,
                                                    float* __restrict__ out) {
    __shared__ float pooled[NB * HDIM];
    __shared__ float ug[NB * HDIM];
    __shared__ float z1[NB * HDIM];
    int t = threadIdx.x;
    for (int i = t; i < NB * HDIM; i += 256) {
        int b = i >> 6, c = i & 63;
        float cnt = fmaxf((float)g_cnt[b], 1.f);
        pooled[i] = g_pool[i] / cnt;
        float s = gb[c];
        #pragma unroll
        for (int k = 0; k < 10; k++) s += u[b * 10 + k] * gW[k * 64 + c];
        ug[i] = fmaxf(s, 0.f);
    }
    __syncthreads();
    for (int i = t; i < NB * HDIM; i += 256) {
        int b = i >> 6, j = i & 63;
        float s = f1b[j];
        #pragma unroll 8
        for (int k = 0; k < 64; k++) s += pooled[b * 64 + k] * f1W[k * 64 + j];
        #pragma unroll 8
        for (int k = 0; k < 64; k++) s += ug[b * 64 + k] * f1W[(64 + k) * 64 + j];
        z1[i] = fmaxf(s, 0.f);
    }
    __syncthreads();
    if (t < NB * 2) {
        int b = t >> 1, o = t & 1;
        float s = f2b[o];
        #pragma unroll 8
        for (int k = 0; k < 64; k++) s += z1[b * 64 + k] * f2W[k * 2 + o];
        out[b * 2 + o] = s;
    }
}

// ---------------- launch ------------------------------------------------------
extern "C" void kernel_launch(void* const* d_in, const int* in_sizes, int n_in,
                              void* d_out, int out_size) {
    const float* x       = (const float*)d_in[0];
    const int*   eidx    = (const int*)d_in[1];
    const float* eattr   = (const float*)d_in[2];
    const float* u       = (const float*)d_in[3];
    const int*   batch   = (const int*)d_in[4];
    const float* node_W  = (const float*)d_in[5];
    const float* node_b  = (const float*)d_in[6];
    const float* eemb_W  = (const float*)d_in[7];
    const float* eemb_b  = (const float*)d_in[8];
    const float* lin_W   = (const float*)d_in[9];
    const float* att_src = (const float*)d_in[10];
    const float* att_dst = (const float*)d_in[11];
    const float* lin_eW  = (const float*)d_in[12];
    const float* att_e   = (const float*)d_in[13];
    const float* conv_b  = (const float*)d_in[14];
    const float* gW      = (const float*)d_in[15];
    const float* gb      = (const float*)d_in[16];
    const float* f1W     = (const float*)d_in[17];
    const float* f1b     = (const float*)d_in[18];
    const float* f2W     = (const float*)d_in[19];
    const float* f2b     = (const float*)d_in[20];
    float* out = (float*)d_out;

    const int* src = eidx;
    const int* dst = eidx + NE;

    void *p_deg, *p_fill;
    cudaGetSymbolAddress(&p_deg,  g_deg);
    cudaGetSymbolAddress(&p_fill, g_fill);

    cudaMemsetAsync(p_deg,  0, NN * sizeof(int));
    cudaMemsetAsync(p_fill, 0, NN * sizeof(int));

    int pre_blocks = PRE_WEATT_BLOCKS + (NN * HDIM + 255) / 256;
    pre_kernel<<<pre_blocks, 256>>>(dst, x, node_W, node_b, lin_eW, att_e, lin_W);
    scan_kernel<<<1, 1024>>>();
    edge_emb_kernel<<<(NE / 2 + 255) / 256, 256>>>(eattr, src, dst, eemb_W, eemb_b);

    for (int l = 0; l < NL; l++) {
        gemm_attn_kernel<<<(NN + 63) / 64, 512>>>(l, att_src + l * NH * 64,
                                                  att_dst + l * NH * 64);
        aggr_kernel<<<(NN / 2 * 32 + 255) / 256, 256>>>(conv_b + l * 64, l, batch);
    }
    final_kernel<<<1, 256>>>(u, gW, gb, f1W, f1b, f2W, f2b, out);
}